// round 4
// baseline (speedup 1.0000x reference)
#include <cuda_runtime.h>
#include <math.h>

typedef unsigned long long u64;

#define BATCH 512
#define TLEN  1024
#define HID   64
#define M_TOTAL (BATCH*TLEN)

__device__ __align__(16) float g_pre[M_TOTAL*HID];
__device__ __align__(16) float g_h1 [M_TOTAL*HID];
__device__ __align__(16) float g_h2 [M_TOTAL*HID];

__device__ __forceinline__ u64 pk2(float x, float y) {
    u64 r; asm("mov.b64 %0,{%1,%2};" : "=l"(r) : "f"(x), "f"(y)); return r;
}
__device__ __forceinline__ void upk2(u64 v, float &x, float &y) {
    asm("mov.b64 {%0,%1},%2;" : "=f"(x), "=f"(y) : "l"(v));
}
#define FMA2(d,a,b,c) asm("fma.rn.f32x2 %0,%1,%2,%3;" : "=l"(d) : "l"(a), "l"(b), "l"(c))
#define ADD2(d,a,b)   asm("add.rn.f32x2 %0,%1,%2;"    : "=l"(d) : "l"(a), "l"(b))

__device__ __forceinline__ float tanh_fast(float x) {
    float xc = fminf(fmaxf(x, -15.0f), 15.0f);
    float e;
    asm("ex2.approx.f32 %0, %1;" : "=f"(e) : "f"(xc * 2.885390081777927f));
    float r;
    asm("rcp.approx.f32 %0, %1;" : "=f"(r) : "f"(e + 1.0f));
    return (e - 1.0f) * r;
}

// ============================================================================
// GEMM (unchanged from R3): 128 threads, 128x64 tile, 8x8 per thread.
// ============================================================================
__global__ void __launch_bounds__(128) gemm64(
    const float* __restrict__ Xext, int xsel,
    const float* __restrict__ W,
    const float* __restrict__ b1, const float* __restrict__ b2,
    float* __restrict__ Oext, int osel, int K)
{
    const float* X = (xsel == 0) ? Xext : (xsel == 1 ? g_h1 : g_h2);
    float* Out     = (osel == 0) ? Oext : g_pre;

    __shared__ __align__(16) u64 Xd[128*32];
    __shared__ __align__(16) u64 Wp[32*32];

    const int tid = threadIdx.x;
    const long m0 = (long)blockIdx.x * 128;

    const int nt  = tid & 7;
    const int mt  = tid >> 3;
    const int np0 = nt * 4;
    const int mr  = mt * 8;
    const int xsw = (mt & 3) << 2;

    u64 acc[8][4];
    {
        u64 bias[4];
        #pragma unroll
        for (int p = 0; p < 4; p++) {
            int n = (np0 + p) * 2;
            float v0 = b1[n], v1 = b1[n+1];
            if (b2) { v0 += b2[n]; v1 += b2[n+1]; }
            bias[p] = pk2(v0, v1);
        }
        #pragma unroll
        for (int i = 0; i < 8; i++)
            #pragma unroll
            for (int p = 0; p < 4; p++) acc[i][p] = bias[p];
    }

    #pragma unroll
    for (int kh = 0; kh < 2; kh++) {
        const int kbase = kh * 32;
        __syncthreads();

        #pragma unroll 8
        for (int i = 0; i < 32; i++) {
            int idx = i * 128 + tid;
            int m  = idx >> 5;
            int kk = idx & 31;
            int k  = kbase + kk;
            float v = (k < K) ? X[(m0 + m) * (long)K + k] : 0.f;
            Xd[m * 32 + (kk ^ (((m >> 3) & 3) << 2))] = pk2(v, v);
        }
        #pragma unroll
        for (int i = 0; i < 8; i++) {
            int idx = i * 128 + tid;
            int np = idx >> 5;
            int kk = idx & 31;
            int k  = kbase + kk;
            float w0 = 0.f, w1 = 0.f;
            if (k < K) {
                w0 = W[(2*np)   * (long)K + k];
                w1 = W[(2*np+1) * (long)K + k];
            }
            Wp[kk * 32 + (np ^ ((kk & 7) << 2))] = pk2(w0, w1);
        }
        __syncthreads();

        #pragma unroll 8
        for (int kk = 0; kk < 32; kk++) {
            int wbase = kk * 32 + (np0 ^ ((kk & 7) << 2));
            ulonglong2 wA = *reinterpret_cast<const ulonglong2*>(&Wp[wbase]);
            ulonglong2 wB = *reinterpret_cast<const ulonglong2*>(&Wp[wbase + 2]);
            const u64* xcol = &Xd[mr * 32 + (kk ^ xsw)];
            #pragma unroll
            for (int i = 0; i < 8; i++) {
                u64 xv = xcol[i * 32];
                FMA2(acc[i][0], xv, wA.x, acc[i][0]);
                FMA2(acc[i][1], xv, wA.y, acc[i][1]);
                FMA2(acc[i][2], xv, wB.x, acc[i][2]);
                FMA2(acc[i][3], xv, wB.y, acc[i][3]);
            }
        }
    }

    const int n0 = np0 * 2;
    #pragma unroll
    for (int i = 0; i < 8; i++) {
        float* dst = &Out[(m0 + mr + i) * 64 + n0];
        ulonglong2 v0, v1;
        v0.x = acc[i][0]; v0.y = acc[i][1];
        v1.x = acc[i][2]; v1.y = acc[i][3];
        *reinterpret_cast<ulonglong2*>(dst)     = v0;
        *reinterpret_cast<ulonglong2*>(dst + 4) = v1;
    }
}

// ============================================================================
// Recurrent scan, k-split x2: 128 threads = 1 batch row; thread (j = tid>>1,
// s = tid&1) computes half of output j's dot (k in [32s, 32s+32)).
// Weights: 16 u64 = 32 regs. h half: 32 floats = 8x LDS.128 (ulonglong2),
// all independent -> full MLP. Halves combined via shfl.bfly(1) (same warp
// since lane partner = tid^1). Time loop unrolled x8 -> static ring indexing
// (fixes R3's local-memory prefetch ring).
// ============================================================================
__global__ void __launch_bounds__(128) rnn_scan(const float* __restrict__ Whh, int osel)
{
    float* Out = (osel == 1) ? g_h1 : g_h2;
    __shared__ __align__(16) float hsm[2][64];

    const int tid = threadIdx.x;
    const int j = tid >> 1;
    const int s = tid & 1;
    const int b = blockIdx.x;

    if (tid < 64) { hsm[0][tid] = 0.f; hsm[1][tid] = 0.f; }
    __syncthreads();

    // w2[q] = {Wh[j][32s+2q], Wh[j][32s+2q+1]}, q=0..15  (16 u64 = 32 regs)
    u64 w2[16];
    {
        const float4* wr = reinterpret_cast<const float4*>(Whh + j*64 + s*32);
        #pragma unroll
        for (int q = 0; q < 8; q++) {
            float4 w = __ldg(&wr[q]);
            w2[2*q]   = pk2(w.x, w.y);
            w2[2*q+1] = pk2(w.z, w.w);
        }
    }

    const float* prow = g_pre + (long)b * TLEN * 64 + j;
    float*       orow = Out   + (long)b * TLEN * 64 + j;

    float pb[8];
    #pragma unroll
    for (int q = 0; q < 8; q++) pb[q] = (s == 0) ? __ldg(&prow[q * 64]) : 0.f;

    int p = 0;
    #pragma unroll 8
    for (int t = 0; t < TLEN; t++) {
        float cur = pb[t & 7];
        if (s == 0 && t + 8 < TLEN) pb[t & 7] = __ldg(&prow[(long)(t + 8) * 64]);

        // This thread's half of h: 32 floats = 16 pairs = 8x ulonglong2.
        const ulonglong2* H2 = reinterpret_cast<const ulonglong2*>(hsm[p]) + 8*s;
        u64 a0 = 0ull, a1 = 0ull, a2 = 0ull, a3 = 0ull;
        #pragma unroll
        for (int q = 0; q < 4; q++) {
            ulonglong2 hA = H2[2*q];      // pairs 4q, 4q+1
            ulonglong2 hB = H2[2*q+1];    // pairs 4q+2, 4q+3
            FMA2(a0, hA.x, w2[4*q+0], a0);
            FMA2(a1, hA.y, w2[4*q+1], a1);
            FMA2(a2, hB.x, w2[4*q+2], a2);
            FMA2(a3, hB.y, w2[4*q+3], a3);
        }
        ADD2(a0, a0, a1); ADD2(a2, a2, a3); ADD2(a0, a0, a2);

        float lo, hi; upk2(a0, lo, hi);
        float sum = lo + hi;
        float oth = __shfl_xor_sync(0xffffffffu, sum, 1);
        float h = tanh_fast(cur + sum + oth);    // meaningful on even lanes

        if (s == 0) {
            orow[(long)t * 64] = h;
            hsm[p ^ 1][j] = h;
        }
        __syncthreads();
        p ^= 1;
    }
}

extern "C" void kernel_launch(void* const* d_in, const int* in_sizes, int n_in,
                              void* d_out, int out_size)
{
    const float* x    = (const float*)d_in[0];
    const float* Wih0 = (const float*)d_in[1];
    const float* Whh0 = (const float*)d_in[2];
    const float* bih0 = (const float*)d_in[3];
    const float* bhh0 = (const float*)d_in[4];
    const float* Wih  = (const float*)d_in[5];
    const float* Whh  = (const float*)d_in[6];
    const float* bih  = (const float*)d_in[7];
    const float* bhh  = (const float*)d_in[8];
    const float* Wfc  = (const float*)d_in[9];
    const float* bfc  = (const float*)d_in[10];
    float* out = (float*)d_out;

    const int GB = M_TOTAL / 128;

    gemm64<<<GB, 128>>>(x, 0, Wih0, bih0, bhh0, nullptr, 3, 52);
    rnn_scan<<<BATCH, 128>>>(Whh0, 1);

    const int insel[3]  = {1, 2, 1};
    const int outsel[3] = {2, 1, 2};
    for (int l = 0; l < 3; l++) {
        gemm64<<<GB, 128>>>(nullptr, insel[l], Wih + l*4096, bih + l*64, bhh + l*64,
                            nullptr, 3, 64);
        rnn_scan<<<BATCH, 128>>>(Whh + l*4096, outsel[l]);
    }

    gemm64<<<GB, 128>>>(nullptr, 2, Wfc, bfc, nullptr, out, 0, 64);
}

// round 5
// speedup vs baseline: 1.1924x; 1.1924x over previous
#include <cuda_runtime.h>
#include <math.h>

typedef unsigned long long u64;

#define BATCH 512
#define TLEN  1024
#define HID   64
#define M_TOTAL (BATCH*TLEN)

__device__ __align__(16) float g_pre[M_TOTAL*HID];
__device__ __align__(16) float g_h1 [M_TOTAL*HID];
__device__ __align__(16) float g_h2 [M_TOTAL*HID];

__device__ __forceinline__ u64 pk2(float x, float y) {
    u64 r; asm("mov.b64 %0,{%1,%2};" : "=l"(r) : "f"(x), "f"(y)); return r;
}
__device__ __forceinline__ void upk2(u64 v, float &x, float &y) {
    asm("mov.b64 {%0,%1},%2;" : "=f"(x), "=f"(y) : "l"(v));
}
#define FMA2(d,a,b,c) asm("fma.rn.f32x2 %0,%1,%2,%3;" : "=l"(d) : "l"(a), "l"(b), "l"(c))
#define ADD2(d,a,b)   asm("add.rn.f32x2 %0,%1,%2;"    : "=l"(d) : "l"(a), "l"(b))

__device__ __forceinline__ float tanh_fast(float x) {
    float xc = fminf(fmaxf(x, -15.0f), 15.0f);
    float e;
    asm("ex2.approx.f32 %0, %1;" : "=f"(e) : "f"(xc * 2.885390081777927f));
    float r;
    asm("rcp.approx.f32 %0, %1;" : "=f"(r) : "f"(e + 1.0f));
    return (e - 1.0f) * r;
}

// ============================================================================
// GEMM (unchanged): 128 threads, 128x64 tile, 8x8 per thread. ~148us/launch.
// ============================================================================
__global__ void __launch_bounds__(128) gemm64(
    const float* __restrict__ Xext, int xsel,
    const float* __restrict__ W,
    const float* __restrict__ b1, const float* __restrict__ b2,
    float* __restrict__ Oext, int osel, int K)
{
    const float* X = (xsel == 0) ? Xext : (xsel == 1 ? g_h1 : g_h2);
    float* Out     = (osel == 0) ? Oext : g_pre;

    __shared__ __align__(16) u64 Xd[128*32];
    __shared__ __align__(16) u64 Wp[32*32];

    const int tid = threadIdx.x;
    const long m0 = (long)blockIdx.x * 128;

    const int nt  = tid & 7;
    const int mt  = tid >> 3;
    const int np0 = nt * 4;
    const int mr  = mt * 8;
    const int xsw = (mt & 3) << 2;

    u64 acc[8][4];
    {
        u64 bias[4];
        #pragma unroll
        for (int p = 0; p < 4; p++) {
            int n = (np0 + p) * 2;
            float v0 = b1[n], v1 = b1[n+1];
            if (b2) { v0 += b2[n]; v1 += b2[n+1]; }
            bias[p] = pk2(v0, v1);
        }
        #pragma unroll
        for (int i = 0; i < 8; i++)
            #pragma unroll
            for (int p = 0; p < 4; p++) acc[i][p] = bias[p];
    }

    #pragma unroll
    for (int kh = 0; kh < 2; kh++) {
        const int kbase = kh * 32;
        __syncthreads();

        #pragma unroll 8
        for (int i = 0; i < 32; i++) {
            int idx = i * 128 + tid;
            int m  = idx >> 5;
            int kk = idx & 31;
            int k  = kbase + kk;
            float v = (k < K) ? X[(m0 + m) * (long)K + k] : 0.f;
            Xd[m * 32 + (kk ^ (((m >> 3) & 3) << 2))] = pk2(v, v);
        }
        #pragma unroll
        for (int i = 0; i < 8; i++) {
            int idx = i * 128 + tid;
            int np = idx >> 5;
            int kk = idx & 31;
            int k  = kbase + kk;
            float w0 = 0.f, w1 = 0.f;
            if (k < K) {
                w0 = W[(2*np)   * (long)K + k];
                w1 = W[(2*np+1) * (long)K + k];
            }
            Wp[kk * 32 + (np ^ ((kk & 7) << 2))] = pk2(w0, w1);
        }
        __syncthreads();

        #pragma unroll 8
        for (int kk = 0; kk < 32; kk++) {
            int wbase = kk * 32 + (np0 ^ ((kk & 7) << 2));
            ulonglong2 wA = *reinterpret_cast<const ulonglong2*>(&Wp[wbase]);
            ulonglong2 wB = *reinterpret_cast<const ulonglong2*>(&Wp[wbase + 2]);
            const u64* xcol = &Xd[mr * 32 + (kk ^ xsw)];
            #pragma unroll
            for (int i = 0; i < 8; i++) {
                u64 xv = xcol[i * 32];
                FMA2(acc[i][0], xv, wA.x, acc[i][0]);
                FMA2(acc[i][1], xv, wA.y, acc[i][1]);
                FMA2(acc[i][2], xv, wB.x, acc[i][2]);
                FMA2(acc[i][3], xv, wB.y, acc[i][3]);
            }
        }
    }

    const int n0 = np0 * 2;
    #pragma unroll
    for (int i = 0; i < 8; i++) {
        float* dst = &Out[(m0 + mr + i) * 64 + n0];
        ulonglong2 v0, v1;
        v0.x = acc[i][0]; v0.y = acc[i][1];
        v1.x = acc[i][2]; v1.y = acc[i][3];
        *reinterpret_cast<ulonglong2*>(dst)     = v0;
        *reinterpret_cast<ulonglong2*>(dst + 4) = v1;
    }
}

// ============================================================================
// Recurrent scan, "p4" layout: h_t = tanh(pre_t + h_{t-1} @ Wh^T), T=1024.
// One row per 64-thread block. Thread (W=warp, s2=lane>>4, jg=lane&15) owns
// 4 outputs {4jg..4jg+3} over 16 k-values [W*32+s2*16, +16):
//   - reads only 16 h-floats (64B) per step  -> 4x less LSU reg-fill than R3/R4
//   - weights: 4x8 u64 = 64 regs (no spill)
// Reduction: shfl_xor(16) combines k-quarters within warp; float4 STS+bar
// combines the two warps; phase-2 is uniform (output o = tid): psum pair read,
// + pre (LDG ring, static idx), tanh, STG out, STS h into double buffer.
// ============================================================================
__global__ void __launch_bounds__(64) rnn_scan(const float* __restrict__ Whh, int osel)
{
    float* Out = (osel == 1) ? g_h1 : g_h2;

    __shared__ __align__(16) float  hbuf[2][64];
    __shared__ __align__(16) float4 psum[2][16];   // [warp][jg] -> 4 partials

    const int tid  = threadIdx.x;
    const int W    = tid >> 5;
    const int lane = tid & 31;
    const int s2   = lane >> 4;
    const int jg   = lane & 15;
    const int K0   = W * 32 + s2 * 16;
    const int b    = blockIdx.x;

    hbuf[0][tid] = 0.f;
    hbuf[1][tid] = 0.f;
    __syncthreads();

    // Weights: w2[o][q] = {Wh[4jg+o][K0+2q], Wh[4jg+o][K0+2q+1]}, o<4, q<8
    u64 w2[4][8];
    #pragma unroll
    for (int o = 0; o < 4; o++) {
        const float4* wr = reinterpret_cast<const float4*>(Whh + (4*jg + o) * 64 + K0);
        #pragma unroll
        for (int q = 0; q < 4; q++) {
            float4 w = __ldg(&wr[q]);
            w2[o][2*q]   = pk2(w.x, w.y);
            w2[o][2*q+1] = pk2(w.z, w.w);
        }
    }

    // Phase-2 column for this thread: o = tid
    const float* prow = g_pre + (long)b * TLEN * 64 + tid;
    float*       orow = Out   + (long)b * TLEN * 64 + tid;

    // 8-deep prefetch ring, statically indexed (loop unrolled x8)
    float pb[8];
    #pragma unroll
    for (int q = 0; q < 8; q++) pb[q] = __ldg(&prow[q * 64]);

    int p = 0;
    #pragma unroll 8
    for (int t = 0; t < TLEN; t++) {
        float cur = pb[t & 7];
        if (t + 8 < TLEN) pb[t & 7] = __ldg(&prow[(long)(t + 8) * 64]);

        // ---- phase 1: partial dots over this thread's 16 k-values
        const ulonglong2* H2 = reinterpret_cast<const ulonglong2*>(&hbuf[p][K0]);
        ulonglong2 hA = H2[0];
        ulonglong2 hB = H2[1];
        ulonglong2 hC = H2[2];
        ulonglong2 hD = H2[3];

        float P[4];
        #pragma unroll
        for (int o = 0; o < 4; o++) {
            u64 a0 = 0ull, a1 = 0ull;
            FMA2(a0, hA.x, w2[o][0], a0);
            FMA2(a1, hA.y, w2[o][1], a1);
            FMA2(a0, hB.x, w2[o][2], a0);
            FMA2(a1, hB.y, w2[o][3], a1);
            FMA2(a0, hC.x, w2[o][4], a0);
            FMA2(a1, hC.y, w2[o][5], a1);
            FMA2(a0, hD.x, w2[o][6], a0);
            FMA2(a1, hD.y, w2[o][7], a1);
            ADD2(a0, a0, a1);
            float lo, hi; upk2(a0, lo, hi);
            P[o] = lo + hi;
        }
        // combine k-quarters within warp
        #pragma unroll
        for (int o = 0; o < 4; o++)
            P[o] += __shfl_xor_sync(0xffffffffu, P[o], 16);

        if (s2 == 0)
            psum[W][jg] = make_float4(P[0], P[1], P[2], P[3]);
        __syncthreads();

        // ---- phase 2: uniform finish, output o = tid
        float part = reinterpret_cast<const float*>(psum[0])[tid]
                   + reinterpret_cast<const float*>(psum[1])[tid];
        float h = tanh_fast(cur + part);

        orow[(long)t * 64] = h;     // 2x 128B stores per row-step
        hbuf[p ^ 1][tid] = h;
        __syncthreads();
        p ^= 1;
    }
}

extern "C" void kernel_launch(void* const* d_in, const int* in_sizes, int n_in,
                              void* d_out, int out_size)
{
    const float* x    = (const float*)d_in[0];
    const float* Wih0 = (const float*)d_in[1];
    const float* Whh0 = (const float*)d_in[2];
    const float* bih0 = (const float*)d_in[3];
    const float* bhh0 = (const float*)d_in[4];
    const float* Wih  = (const float*)d_in[5];
    const float* Whh  = (const float*)d_in[6];
    const float* bih  = (const float*)d_in[7];
    const float* bhh  = (const float*)d_in[8];
    const float* Wfc  = (const float*)d_in[9];
    const float* bfc  = (const float*)d_in[10];
    float* out = (float*)d_out;

    const int GB = M_TOTAL / 128;

    gemm64<<<GB, 128>>>(x, 0, Wih0, bih0, bhh0, nullptr, 3, 52);
    rnn_scan<<<BATCH, 64>>>(Whh0, 1);

    const int insel[3]  = {1, 2, 1};
    const int outsel[3] = {2, 1, 2};
    for (int l = 0; l < 3; l++) {
        gemm64<<<GB, 128>>>(nullptr, insel[l], Wih + l*4096, bih + l*64, bhh + l*64,
                            nullptr, 3, 64);
        rnn_scan<<<BATCH, 64>>>(Whh + l*4096, outsel[l]);
    }

    gemm64<<<GB, 128>>>(nullptr, 2, Wfc, bfc, nullptr, out, 0, 64);
}

// round 7
// speedup vs baseline: 1.2471x; 1.0459x over previous
#include <cuda_runtime.h>
#include <math.h>

typedef unsigned long long u64;

#define BATCH  512
#define TLEN   1024
#define HID    64
#define M_TOTAL (BATCH*TLEN)
#define CHUNKS 8
#define CT     (TLEN/CHUNKS)          // 128 steps per chunk
#define GROUPS 9                      // per chunk: g0 gemm0,g1 scan0,...,g7 scan3,g8 fc
#define BLOCKS_TOTAL (CHUNKS*GROUPS*BATCH)

// Per-layer scratch (single-writer/single-reader per launch).
__device__ __align__(16) float g_pre [4][M_TOTAL*HID];
__device__ __align__(16) float g_hout[4][M_TOTAL*HID];
__device__ __align__(16) float g_hst [4][BATCH*HID];    // h carry between chunks

// Dependency flags: one int per (layer, chunk, row). Set to 1 by producer.
__device__ int gflag[4][CHUNKS][BATCH];   // pre(l, chunk c, row b) ready
__device__ int sflag[4][CHUNKS][BATCH];   // h  (l, chunk c, row b) ready

__device__ __forceinline__ int ld_acq(const int* p) {
    int v;
    asm volatile("ld.acquire.gpu.global.b32 %0, [%1];" : "=r"(v) : "l"(p) : "memory");
    return v;
}
__device__ __forceinline__ void st_rel(int* p, int v) {
    asm volatile("st.release.gpu.global.b32 [%0], %1;" :: "l"(p), "r"(v) : "memory");
}

__device__ __forceinline__ u64 pk2(float x, float y) {
    u64 r; asm("mov.b64 %0,{%1,%2};" : "=l"(r) : "f"(x), "f"(y)); return r;
}
__device__ __forceinline__ void upk2(u64 v, float &x, float &y) {
    asm("mov.b64 {%0,%1},%2;" : "=f"(x), "=f"(y) : "l"(v));
}
#define FMA2(d,a,b,c) asm("fma.rn.f32x2 %0,%1,%2,%3;" : "=l"(d) : "l"(a), "l"(b), "l"(c))
#define ADD2(d,a,b)   asm("add.rn.f32x2 %0,%1,%2;"    : "=l"(d) : "l"(a), "l"(b))

__device__ __forceinline__ float tanh_fast(float x) {
    float xc = fminf(fmaxf(x, -15.0f), 15.0f);
    float e;
    asm("ex2.approx.f32 %0, %1;" : "=f"(e) : "f"(xc * 2.885390081777927f));
    float r;
    asm("rcp.approx.f32 %0, %1;" : "=f"(r) : "f"(e + 1.0f));
    return (e - 1.0f) * r;
}

// ============================================================================
// GEMM tile body (proven R5 kernel, chunk-parameterized): 128 threads,
// 128 rows (= one row-chunk: m = b*TLEN + t0 + i) x 64 cols, 8x8 per thread.
// ============================================================================
__device__ __forceinline__ void gemm_body(
    const float* __restrict__ X, const float* __restrict__ W,
    const float* __restrict__ b1, const float* __restrict__ b2,
    float* __restrict__ Out, int K, long m0)
{
    __shared__ __align__(16) u64 Xd[128*32];
    __shared__ __align__(16) u64 Wp[32*32];

    const int tid = threadIdx.x;
    const int nt  = tid & 7;
    const int mt  = tid >> 3;
    const int np0 = nt * 4;
    const int mr  = mt * 8;
    const int xsw = (mt & 3) << 2;

    u64 acc[8][4];
    {
        u64 bias[4];
        #pragma unroll
        for (int p = 0; p < 4; p++) {
            int n = (np0 + p) * 2;
            float v0 = b1[n], v1 = b1[n+1];
            if (b2) { v0 += b2[n]; v1 += b2[n+1]; }
            bias[p] = pk2(v0, v1);
        }
        #pragma unroll
        for (int i = 0; i < 8; i++)
            #pragma unroll
            for (int p = 0; p < 4; p++) acc[i][p] = bias[p];
    }

    #pragma unroll
    for (int kh = 0; kh < 2; kh++) {
        const int kbase = kh * 32;
        __syncthreads();

        #pragma unroll 8
        for (int i = 0; i < 32; i++) {
            int idx = i * 128 + tid;
            int m  = idx >> 5;
            int kk = idx & 31;
            int k  = kbase + kk;
            float v = (k < K) ? X[(m0 + m) * (long)K + k] : 0.f;
            Xd[m * 32 + (kk ^ (((m >> 3) & 3) << 2))] = pk2(v, v);
        }
        #pragma unroll
        for (int i = 0; i < 8; i++) {
            int idx = i * 128 + tid;
            int np = idx >> 5;
            int kk = idx & 31;
            int k  = kbase + kk;
            float w0 = 0.f, w1 = 0.f;
            if (k < K) {
                w0 = W[(2*np)   * (long)K + k];
                w1 = W[(2*np+1) * (long)K + k];
            }
            Wp[kk * 32 + (np ^ ((kk & 7) << 2))] = pk2(w0, w1);
        }
        __syncthreads();

        #pragma unroll 8
        for (int kk = 0; kk < 32; kk++) {
            int wbase = kk * 32 + (np0 ^ ((kk & 7) << 2));
            ulonglong2 wA = *reinterpret_cast<const ulonglong2*>(&Wp[wbase]);
            ulonglong2 wB = *reinterpret_cast<const ulonglong2*>(&Wp[wbase + 2]);
            const u64* xcol = &Xd[mr * 32 + (kk ^ xsw)];
            #pragma unroll
            for (int i = 0; i < 8; i++) {
                u64 xv = xcol[i * 32];
                FMA2(acc[i][0], xv, wA.x, acc[i][0]);
                FMA2(acc[i][1], xv, wA.y, acc[i][1]);
                FMA2(acc[i][2], xv, wB.x, acc[i][2]);
                FMA2(acc[i][3], xv, wB.y, acc[i][3]);
            }
        }
    }

    const int n0 = np0 * 2;
    #pragma unroll
    for (int i = 0; i < 8; i++) {
        float* dst = &Out[(m0 + mr + i) * 64 + n0];
        ulonglong2 v0, v1;
        v0.x = acc[i][0]; v0.y = acc[i][1];
        v1.x = acc[i][2]; v1.y = acc[i][3];
        *reinterpret_cast<ulonglong2*>(dst)     = v0;
        *reinterpret_cast<ulonglong2*>(dst + 4) = v1;
    }
}

// ============================================================================
// Flag-reset kernel (flags must be zero at the start of every replay).
// ============================================================================
__global__ void zero_flags()
{
    int idx = blockIdx.x * blockDim.x + threadIdx.x;
    int* g = &gflag[0][0][0];
    int* s = &sflag[0][0][0];
    const int N = 4 * CHUNKS * BATCH;
    if (idx < N) { g[idx] = 0; s[idx] = 0; }
}

// ============================================================================
// Megakernel: the whole 4-layer RNN + FC as a self-timed wavefront.
// bid -> (chunk c, group g, row b), topologically ordered:
//   g = 2l   : GEMM  pre(l, c, b)   [deps: sflag[l-1][c][b] for l>=1]
//   g = 2l+1 : SCAN  h(l, c, b)     [deps: gflag[l][c][b], sflag[l][c-1][b]]
//   g = 8    : FC    out(c, b)      [deps: sflag[3][c][b]]
// Producers: threadfence + bar + tid0 st.release. Consumers: tid0 spin
// ld.acquire (+nanosleep), threadfence (CCTL.IVALL), bar.
// ============================================================================
__global__ void __launch_bounds__(128, 4) mega(
    const float* __restrict__ x,
    const float* __restrict__ Wih0, const float* __restrict__ Whh0,
    const float* __restrict__ bih0, const float* __restrict__ bhh0,
    const float* __restrict__ Wih,  const float* __restrict__ Whh,
    const float* __restrict__ bih,  const float* __restrict__ bhh,
    const float* __restrict__ Wfc,  const float* __restrict__ bfc,
    float* __restrict__ out)
{
    const int bid = blockIdx.x;
    const int c   = bid / (GROUPS * BATCH);
    const int r   = bid % (GROUPS * BATCH);
    const int g   = r / BATCH;
    const int b   = r % BATCH;
    const int t0  = c * CT;
    const int tid = threadIdx.x;

    if (g == 8) {
        // ---------------- FC chunk ----------------
        if (tid == 0) {
            while (ld_acq(&sflag[3][c][b]) == 0) __nanosleep(64);
            __threadfence();
        }
        __syncthreads();
        gemm_body(&g_hout[3][0], Wfc, bfc, nullptr, out, 64, (long)b*TLEN + t0);
        return;
    }

    const int l = g >> 1;

    if ((g & 1) == 0) {
        // ---------------- GEMM: pre(l, c) ----------------
        if (tid == 0) {
            if (l > 0) while (ld_acq(&sflag[l-1][c][b]) == 0) __nanosleep(64);
            __threadfence();
        }
        __syncthreads();

        const float* X  = (l == 0) ? x : &g_hout[l-1][0];
        const int    K  = (l == 0) ? 52 : 64;
        const float* W  = (l == 0) ? Wih0 : Wih + (l-1)*4096;
        const float* b1 = (l == 0) ? bih0 : bih + (l-1)*64;
        const float* b2 = (l == 0) ? bhh0 : bhh + (l-1)*64;
        gemm_body(X, W, b1, b2, &g_pre[l][0], K, (long)b*TLEN + t0);

        __threadfence();
        __syncthreads();
        if (tid == 0) st_rel(&gflag[l][c][b], 1);
        return;
    }

    // ---------------- SCAN: h(l, c) ----------------
    const float* Whh_l = (l == 0) ? Whh0 : Whh + (l-1)*4096;
    float* pre  = &g_pre [l][0];
    float* hout = &g_hout[l][0];
    float* hst  = &g_hst [l][0];

    __shared__ __align__(16) float  hbuf[2][64];
    __shared__ __align__(16) float4 psum[2][16];
    __shared__ __align__(16) float  psm[8][64];     // pre staging ring

    if (tid == 0) {
        while (ld_acq(&gflag[l][c][b]) == 0) __nanosleep(64);
        if (c > 0) while (ld_acq(&sflag[l][c-1][b]) == 0) __nanosleep(64);
        __threadfence();    // invalidate L1 (g_hst line reused across chunks)
    }
    __syncthreads();   // bar0: everyone waits for deps

    if (tid < 64) {
        // ===== critical warps: recurrence only (no LDG/STG) =====
        const int W32  = tid >> 5;
        const int lane = tid & 31;
        const int s2   = lane >> 4;
        const int jg   = lane & 15;
        const int K0   = W32 * 32 + s2 * 16;

        float h0v = (c == 0) ? 0.f : __ldcg(&hst[b*64 + tid]);
        hbuf[0][tid] = h0v;
        hbuf[1][tid] = h0v;

        u64 w2[4][8];
        #pragma unroll
        for (int o = 0; o < 4; o++) {
            const float4* wr = reinterpret_cast<const float4*>(Whh_l + (4*jg + o)*64 + K0);
            #pragma unroll
            for (int q = 0; q < 4; q++) {
                float4 w = __ldg(&wr[q]);
                w2[o][2*q]   = pk2(w.x, w.y);
                w2[o][2*q+1] = pk2(w.z, w.w);
            }
        }
        __syncthreads();   // init bar (matches upper prefill bar)

        #pragma unroll 8
        for (int t = 0; t < CT; t++) {
            const ulonglong2* H2 = reinterpret_cast<const ulonglong2*>(&hbuf[t & 1][K0]);
            ulonglong2 hA = H2[0];
            ulonglong2 hB = H2[1];
            ulonglong2 hC = H2[2];
            ulonglong2 hD = H2[3];

            float P[4];
            #pragma unroll
            for (int o = 0; o < 4; o++) {
                u64 a0 = 0ull, a1 = 0ull;
                FMA2(a0, hA.x, w2[o][0], a0);
                FMA2(a1, hA.y, w2[o][1], a1);
                FMA2(a0, hB.x, w2[o][2], a0);
                FMA2(a1, hB.y, w2[o][3], a1);
                FMA2(a0, hC.x, w2[o][4], a0);
                FMA2(a1, hC.y, w2[o][5], a1);
                FMA2(a0, hD.x, w2[o][6], a0);
                FMA2(a1, hD.y, w2[o][7], a1);
                ADD2(a0, a0, a1);
                float lo, hi; upk2(a0, lo, hi);
                P[o] = lo + hi;
            }
            #pragma unroll
            for (int o = 0; o < 4; o++)
                P[o] += __shfl_xor_sync(0xffffffffu, P[o], 16);

            if (s2 == 0)
                psum[W32][jg] = make_float4(P[0], P[1], P[2], P[3]);
            __syncthreads();   // bar A

            float part = reinterpret_cast<const float*>(psum[0])[tid]
                       + reinterpret_cast<const float*>(psum[1])[tid];
            float cur  = psm[t & 7][tid];
            float h = tanh_fast(cur + part);
            hbuf[(t & 1) ^ 1][tid] = h;
            __syncthreads();   // bar B
        }
        hst[b*64 + tid] = hbuf[0][tid];   // CT even -> h_{CT-1} in hbuf[0]
    } else {
        // ===== service warps: pre prefetch into psm ring + h drain to global =====
        const int u = tid - 64;
        const float* prow = pre  + ((long)b * TLEN + t0) * 64 + u;
        float*       orow = hout + ((long)b * TLEN + t0) * 64 + u;

        #pragma unroll
        for (int q = 0; q < 4; q++) psm[q][u] = __ldg(&prow[q * 64]);
        float rp[4];
        #pragma unroll
        for (int q = 0; q < 4; q++) rp[q] = __ldg(&prow[(4 + q) * 64]);
        __syncthreads();   // init bar

        #pragma unroll 8
        for (int t = 0; t < CT; t++) {
            float v = rp[t & 3];                        // value for time t+4
            if (t + 8 < CT) rp[t & 3] = __ldg(&prow[(long)(t + 8) * 64]);
            float hprev = hbuf[t & 1][u];               // h_{t-1} (junk at t=0)
            __syncthreads();   // bar A
            if (t + 4 < CT) psm[(t + 4) & 7][u] = v;
            if (t >= 1) orow[(long)(t - 1) * 64] = hprev;
            __syncthreads();   // bar B
        }
        orow[(long)(CT - 1) * 64] = hbuf[CT & 1][u];
    }

    __threadfence();
    __syncthreads();
    if (tid == 0) st_rel(&sflag[l][c][b], 1);
}

// ============================================================================
// Launch: flag reset + megakernel. Single stream, 2 launches, no allocations,
// graph-capturable.
// ============================================================================
extern "C" void kernel_launch(void* const* d_in, const int* in_sizes, int n_in,
                              void* d_out, int out_size)
{
    const float* x    = (const float*)d_in[0];
    const float* Wih0 = (const float*)d_in[1];
    const float* Whh0 = (const float*)d_in[2];
    const float* bih0 = (const float*)d_in[3];
    const float* bhh0 = (const float*)d_in[4];
    const float* Wih  = (const float*)d_in[5];
    const float* Whh  = (const float*)d_in[6];
    const float* bih  = (const float*)d_in[7];
    const float* bhh  = (const float*)d_in[8];
    const float* Wfc  = (const float*)d_in[9];
    const float* bfc  = (const float*)d_in[10];
    float* out = (float*)d_out;

    zero_flags<<<(4*CHUNKS*BATCH + 255)/256, 256>>>();
    mega<<<BLOCKS_TOTAL, 128>>>(x, Wih0, Whh0, bih0, bhh0,
                                Wih, Whh, bih, bhh, Wfc, bfc, out);
}